// round 1
// baseline (speedup 1.0000x reference)
#include <cuda_runtime.h>
#include <math.h>

#define NT 2048   // tokens
#define NH 2048   // hidden
#define NI 1408   // intermediate
#define NE 8      // experts
#define TK 2      // top-k
#define NP (NT*TK)

// ---------------- scratch (no allocs allowed) ----------------
__device__ int   g_cnt[NE];
__device__ int   g_fill[NE];
__device__ int   g_off[NE + 1];
__device__ int   g_tok[NP];
__device__ float g_wt[NP];
__device__ float g_act[(size_t)NP * NI];   // ~23 MB silu(g)*u per routed pair

// ---------------- routing ----------------
__global__ void k_reset() {
    int i = threadIdx.x;
    if (i < NE) { g_cnt[i] = 0; g_fill[i] = 0; }
}

__global__ void k_count(const int* __restrict__ idx) {
    int i = blockIdx.x * blockDim.x + threadIdx.x;
    if (i < NP) atomicAdd(&g_cnt[idx[i]], 1);
}

__global__ void k_scan() {
    if (threadIdx.x == 0) {
        int s = 0;
        for (int e = 0; e < NE; e++) { g_off[e] = s; s += g_cnt[e]; }
        g_off[NE] = s;
    }
}

__global__ void k_fill(const int* __restrict__ idx, const float* __restrict__ w) {
    int i = blockIdx.x * blockDim.x + threadIdx.x;
    if (i < NP) {
        int e = idx[i];
        int pos = g_off[e] + atomicAdd(&g_fill[e], 1);
        g_tok[pos] = i / TK;
        g_wt[pos]  = w[i];
    }
}

__global__ void k_zero(float* __restrict__ out) {
    int i = blockIdx.x * blockDim.x + threadIdx.x;
    ((float4*)out)[i] = make_float4(0.f, 0.f, 0.f, 0.f);
}

// ---------------- GEMM1: act = silu(X Wg) * (X Wu), gathered rows ----------------
// Tile 64x64, K-step 16, 256 threads, 4x4 microtile per thread (x2 matrices)
__global__ __launch_bounds__(256) void k_gemm1(
    const float* __restrict__ hidden,
    const float* __restrict__ gate_w,
    const float* __restrict__ up_w)
{
    int e   = blockIdx.z;
    int cnt = g_cnt[e];
    int m0  = blockIdx.y * 64;
    if (m0 >= cnt) return;
    int base = g_off[e];
    int n0   = blockIdx.x * 64;

    __shared__ float As[16][68];
    __shared__ float Bg[16][68];
    __shared__ float Bu[16][68];
    __shared__ int   toks[64];

    int tid = threadIdx.x;
    if (tid < 64) {
        int m = m0 + tid;
        toks[tid] = (m < cnt) ? g_tok[base + m] : 0;
    }
    __syncthreads();

    int tx = tid & 15, ty = tid >> 4;
    int a_m = tid >> 2, a_k = (tid & 3) << 2;
    int b_k = tid >> 4, b_n = (tid & 15) << 2;

    const float* gp   = gate_w + (size_t)e * NH * NI;
    const float* up   = up_w   + (size_t)e * NH * NI;
    const float* arow = hidden + (size_t)toks[a_m] * NH + a_k;

    float accg[4][4] = {}, accu[4][4] = {};

    for (int k0 = 0; k0 < NH; k0 += 16) {
        float4 av = *(const float4*)(arow + k0);
        As[a_k + 0][a_m] = av.x;
        As[a_k + 1][a_m] = av.y;
        As[a_k + 2][a_m] = av.z;
        As[a_k + 3][a_m] = av.w;
        *(float4*)&Bg[b_k][b_n] = *(const float4*)(gp + (size_t)(k0 + b_k) * NI + n0 + b_n);
        *(float4*)&Bu[b_k][b_n] = *(const float4*)(up + (size_t)(k0 + b_k) * NI + n0 + b_n);
        __syncthreads();

#pragma unroll
        for (int kk = 0; kk < 16; kk++) {
            float4 a4  = *(const float4*)&As[kk][ty << 2];
            float4 bg4 = *(const float4*)&Bg[kk][tx << 2];
            float4 bu4 = *(const float4*)&Bu[kk][tx << 2];
            float a[4]  = {a4.x, a4.y, a4.z, a4.w};
            float bg[4] = {bg4.x, bg4.y, bg4.z, bg4.w};
            float bu[4] = {bu4.x, bu4.y, bu4.z, bu4.w};
#pragma unroll
            for (int i = 0; i < 4; i++)
#pragma unroll
                for (int j = 0; j < 4; j++) {
                    accg[i][j] += a[i] * bg[j];
                    accu[i][j] += a[i] * bu[j];
                }
        }
        __syncthreads();
    }

#pragma unroll
    for (int i = 0; i < 4; i++) {
        int m = m0 + (ty << 2) + i;
        if (m < cnt) {
            float4 v;
            float* vp = (float*)&v;
#pragma unroll
            for (int j = 0; j < 4; j++) {
                float g = accg[i][j];
                float u = accu[i][j];
                float s = g / (1.f + __expf(-g));
                vp[j] = s * u;
            }
            *(float4*)(g_act + (size_t)(base + m) * NI + n0 + (tx << 2)) = v;
        }
    }
}

// ---------------- GEMM2: out[token] += wt * (act · Wd) ----------------
__global__ __launch_bounds__(256) void k_gemm2(
    const float* __restrict__ down_w,
    float* __restrict__ out)
{
    int e   = blockIdx.z;
    int cnt = g_cnt[e];
    int m0  = blockIdx.y * 64;
    if (m0 >= cnt) return;
    int base = g_off[e];
    int n0   = blockIdx.x * 64;

    __shared__ float As[16][68];
    __shared__ float Bs[16][68];
    __shared__ int   toks[64];
    __shared__ float wts[64];

    int tid = threadIdx.x;
    if (tid < 64) {
        int m = m0 + tid;
        toks[tid] = (m < cnt) ? g_tok[base + m] : 0;
        wts[tid]  = (m < cnt) ? g_wt[base + m] : 0.f;
    }
    __syncthreads();

    int tx = tid & 15, ty = tid >> 4;
    int a_m = tid >> 2, a_k = (tid & 3) << 2;
    int b_k = tid >> 4, b_n = (tid & 15) << 2;

    int arow = m0 + a_m;
    if (arow >= cnt) arow = 0;                 // clamp to a valid row (writes guarded)
    const float* ap = g_act + (size_t)(base + arow) * NI + a_k;
    const float* dp = down_w + (size_t)e * NI * NH;

    float acc[4][4] = {};

    for (int k0 = 0; k0 < NI; k0 += 16) {
        float4 av = *(const float4*)(ap + k0);
        As[a_k + 0][a_m] = av.x;
        As[a_k + 1][a_m] = av.y;
        As[a_k + 2][a_m] = av.z;
        As[a_k + 3][a_m] = av.w;
        *(float4*)&Bs[b_k][b_n] = *(const float4*)(dp + (size_t)(k0 + b_k) * NH + n0 + b_n);
        __syncthreads();

#pragma unroll
        for (int kk = 0; kk < 16; kk++) {
            float4 a4 = *(const float4*)&As[kk][ty << 2];
            float4 b4 = *(const float4*)&Bs[kk][tx << 2];
            float a[4] = {a4.x, a4.y, a4.z, a4.w};
            float b[4] = {b4.x, b4.y, b4.z, b4.w};
#pragma unroll
            for (int i = 0; i < 4; i++)
#pragma unroll
                for (int j = 0; j < 4; j++)
                    acc[i][j] += a[i] * b[j];
        }
        __syncthreads();
    }

#pragma unroll
    for (int i = 0; i < 4; i++) {
        int lm = (ty << 2) + i;
        int m  = m0 + lm;
        if (m < cnt) {
            int   t = toks[lm];
            float w = wts[lm];
            float* dst = out + (size_t)t * NH + n0 + (tx << 2);
#pragma unroll
            for (int j = 0; j < 4; j++)
                atomicAdd(dst + j, w * acc[i][j]);
        }
    }
}

// ---------------- launch ----------------
extern "C" void kernel_launch(void* const* d_in, const int* in_sizes, int n_in,
                              void* d_out, int out_size)
{
    const float* hidden = (const float*)d_in[0];
    const int*   idx    = (const int*)  d_in[1];
    const float* topw   = (const float*)d_in[2];
    const float* gate_w = (const float*)d_in[3];
    const float* up_w   = (const float*)d_in[4];
    const float* down_w = (const float*)d_in[5];
    float* out = (float*)d_out;

    k_reset<<<1, 32>>>();
    k_count<<<NP / 256, 256>>>(idx);
    k_scan<<<1, 32>>>();
    k_fill<<<NP / 256, 256>>>(idx, topw);
    k_zero<<<(NT * NH / 4) / 256, 256>>>(out);

    dim3 g1(NI / 64, NP / 64, NE);
    k_gemm1<<<g1, 256>>>(hidden, gate_w, up_w);

    dim3 g2(NH / 64, NP / 64, NE);
    k_gemm2<<<g2, 256>>>(down_w, out);
}

// round 2
// speedup vs baseline: 1.9132x; 1.9132x over previous
#include <cuda_runtime.h>
#include <math.h>

#define NT 2048
#define NH 2048
#define NI 1408
#define NE 8
#define TK 2
#define NP (NT*TK)

#define BM   128
#define BN   64
#define BK   32
#define ASTR 136   // stride%32==8 -> conflict-free 8t+g fragment pattern
#define BSTR 72

// ---------------- scratch ----------------
__device__ int   g_cnt[NE];
__device__ int   g_fill[NE];
__device__ int   g_off[NE + 1];
__device__ int   g_tok[NP];
__device__ float g_wt[NP];
__device__ float g_act[(size_t)NP * NI];

// ---------------- routing ----------------
__global__ void k_reset() {
    int i = threadIdx.x;
    if (i < NE) { g_cnt[i] = 0; g_fill[i] = 0; }
}
__global__ void k_count(const int* __restrict__ idx) {
    int i = blockIdx.x * blockDim.x + threadIdx.x;
    if (i < NP) atomicAdd(&g_cnt[idx[i]], 1);
}
__global__ void k_scan() {
    if (threadIdx.x == 0) {
        int s = 0;
        for (int e = 0; e < NE; e++) { g_off[e] = s; s += g_cnt[e]; }
        g_off[NE] = s;
    }
}
__global__ void k_fill(const int* __restrict__ idx, const float* __restrict__ w) {
    int i = blockIdx.x * blockDim.x + threadIdx.x;
    if (i < NP) {
        int e = idx[i];
        int pos = g_off[e] + atomicAdd(&g_fill[e], 1);
        g_tok[pos] = i / TK;
        g_wt[pos]  = w[i];
    }
}
__global__ void k_zero(float* __restrict__ out) {
    int i = blockIdx.x * blockDim.x + threadIdx.x;
    ((float4*)out)[i] = make_float4(0.f, 0.f, 0.f, 0.f);
}

// ---------------- tf32 mma helpers ----------------
__device__ __forceinline__ unsigned f2tf(float f) {
    unsigned r;
    asm("cvt.rna.tf32.f32 %0, %1;" : "=r"(r) : "f"(f));
    return r;
}
__device__ __forceinline__ void mma8(float* c, const unsigned* a, const unsigned* b) {
    asm volatile(
        "mma.sync.aligned.m16n8k8.row.col.f32.tf32.tf32.f32 "
        "{%0,%1,%2,%3},{%4,%5,%6,%7},{%8,%9},{%0,%1,%2,%3};"
        : "+f"(c[0]), "+f"(c[1]), "+f"(c[2]), "+f"(c[3])
        : "r"(a[0]), "r"(a[1]), "r"(a[2]), "r"(a[3]), "r"(b[0]), "r"(b[1]));
}

// ---------------- GEMM1: act = silu(X Wg) * (X Wu), gathered rows ----------------
// BM=128 x BN=64, BK=32. 8 warps: 4(M) x 2(N). Warp tile 32x32 dual-matrix.
__global__ __launch_bounds__(256) void k_gemm1(
    const float* __restrict__ hidden,
    const float* __restrict__ gate_w,
    const float* __restrict__ up_w)
{
    __shared__ unsigned As[BK][ASTR];
    __shared__ unsigned Bg[BK][BSTR];
    __shared__ unsigned Bu[BK][BSTR];
    __shared__ int toks[BM];

    int e = blockIdx.z, cnt = g_cnt[e];
    int m0 = blockIdx.y * BM;
    if (m0 >= cnt) return;
    int base = g_off[e];
    int n0 = blockIdx.x * BN;
    int tid = threadIdx.x;

    if (tid < BM) {
        int m = m0 + tid;
        toks[tid] = (m < cnt) ? g_tok[base + m] : g_tok[base];
    }
    __syncthreads();

    const float* gp = gate_w + (size_t)e * NH * NI;
    const float* up = up_w   + (size_t)e * NH * NI;

    // staging coordinates
    int a_m = tid >> 3, a_k = (tid & 7) << 2;          // + p*32 rows, 4 passes
    int b_k = tid >> 4, b_n = (tid & 15) << 2;         // + p*16 rows, 2 passes

    // initial stage (k0 = 0)
#pragma unroll
    for (int p = 0; p < 4; p++) {
        int m = a_m + p * 32;
        float4 v = *(const float4*)(hidden + (size_t)toks[m] * NH + a_k);
        As[a_k + 0][m] = f2tf(v.x); As[a_k + 1][m] = f2tf(v.y);
        As[a_k + 2][m] = f2tf(v.z); As[a_k + 3][m] = f2tf(v.w);
    }
#pragma unroll
    for (int p = 0; p < 2; p++) {
        int k = b_k + p * 16;
        float4 vg = *(const float4*)(gp + (size_t)k * NI + n0 + b_n);
        float4 vu = *(const float4*)(up + (size_t)k * NI + n0 + b_n);
        Bg[k][b_n+0]=f2tf(vg.x); Bg[k][b_n+1]=f2tf(vg.y); Bg[k][b_n+2]=f2tf(vg.z); Bg[k][b_n+3]=f2tf(vg.w);
        Bu[k][b_n+0]=f2tf(vu.x); Bu[k][b_n+1]=f2tf(vu.y); Bu[k][b_n+2]=f2tf(vu.z); Bu[k][b_n+3]=f2tf(vu.w);
    }
    __syncthreads();

    int lane = tid & 31, wid = tid >> 5;
    int wm = (wid & 3) * 32, wn = (wid >> 2) * 32;
    int grp = lane >> 2, tig = lane & 3;

    float accg[2][4][4] = {}, accu[2][4][4] = {};
    float4 pa[4], pg[2], pu[2];

    for (int k0 = 0; k0 < NH; k0 += BK) {
        bool nxt = (k0 + BK) < NH;
        if (nxt) {
            int kn = k0 + BK;
#pragma unroll
            for (int p = 0; p < 4; p++)
                pa[p] = *(const float4*)(hidden + (size_t)toks[a_m + p*32] * NH + kn + a_k);
#pragma unroll
            for (int p = 0; p < 2; p++) {
                int k = b_k + p * 16;
                pg[p] = *(const float4*)(gp + (size_t)(kn + k) * NI + n0 + b_n);
                pu[p] = *(const float4*)(up + (size_t)(kn + k) * NI + n0 + b_n);
            }
        }

#pragma unroll
        for (int kk = 0; kk < 4; kk++) {
            int k8 = kk * 8;
            unsigned a[2][4];
#pragma unroll
            for (int mi = 0; mi < 2; mi++) {
                int mb = wm + mi * 16 + grp;
                a[mi][0] = As[k8 + tig    ][mb];
                a[mi][1] = As[k8 + tig    ][mb + 8];
                a[mi][2] = As[k8 + tig + 4][mb];
                a[mi][3] = As[k8 + tig + 4][mb + 8];
            }
#pragma unroll
            for (int nj = 0; nj < 4; nj++) {
                int nb = wn + nj * 8 + grp;
                unsigned b[2];
                b[0] = Bg[k8 + tig][nb]; b[1] = Bg[k8 + tig + 4][nb];
                mma8(accg[0][nj], a[0], b);
                mma8(accg[1][nj], a[1], b);
                b[0] = Bu[k8 + tig][nb]; b[1] = Bu[k8 + tig + 4][nb];
                mma8(accu[0][nj], a[0], b);
                mma8(accu[1][nj], a[1], b);
            }
        }
        __syncthreads();
        if (nxt) {
#pragma unroll
            for (int p = 0; p < 4; p++) {
                int m = a_m + p * 32;
                As[a_k+0][m]=f2tf(pa[p].x); As[a_k+1][m]=f2tf(pa[p].y);
                As[a_k+2][m]=f2tf(pa[p].z); As[a_k+3][m]=f2tf(pa[p].w);
            }
#pragma unroll
            for (int p = 0; p < 2; p++) {
                int k = b_k + p * 16;
                Bg[k][b_n+0]=f2tf(pg[p].x); Bg[k][b_n+1]=f2tf(pg[p].y);
                Bg[k][b_n+2]=f2tf(pg[p].z); Bg[k][b_n+3]=f2tf(pg[p].w);
                Bu[k][b_n+0]=f2tf(pu[p].x); Bu[k][b_n+1]=f2tf(pu[p].y);
                Bu[k][b_n+2]=f2tf(pu[p].z); Bu[k][b_n+3]=f2tf(pu[p].w);
            }
            __syncthreads();
        }
    }

    // epilogue: silu(g)*u -> g_act
#pragma unroll
    for (int mi = 0; mi < 2; mi++) {
#pragma unroll
        for (int nj = 0; nj < 4; nj++) {
            int mrow = wm + mi * 16 + grp;          // local row in tile
            int ncol = n0 + wn + nj * 8 + tig * 2;
#pragma unroll
            for (int h = 0; h < 2; h++) {           // h=0: row, h=1: row+8
                int mr = m0 + mrow + h * 8;
                if (mr < cnt) {
                    float g0 = accg[mi][nj][2*h],     u0 = accu[mi][nj][2*h];
                    float g1 = accg[mi][nj][2*h + 1], u1 = accu[mi][nj][2*h + 1];
                    float2 v;
                    v.x = (g0 / (1.f + __expf(-g0))) * u0;
                    v.y = (g1 / (1.f + __expf(-g1))) * u1;
                    *(float2*)(g_act + (size_t)(base + mr) * NI + ncol) = v;
                }
            }
        }
    }
}

// ---------------- GEMM2: out[token] += wt * (act . Wd) ----------------
__global__ __launch_bounds__(256) void k_gemm2(
    const float* __restrict__ down_w,
    float* __restrict__ out)
{
    __shared__ unsigned As[BK][ASTR];
    __shared__ unsigned Bs[BK][BSTR];
    __shared__ int   toks[BM];
    __shared__ float wts[BM];

    int e = blockIdx.z, cnt = g_cnt[e];
    int m0 = blockIdx.y * BM;
    if (m0 >= cnt) return;
    int base = g_off[e];
    int n0 = blockIdx.x * BN;
    int tid = threadIdx.x;

    if (tid < BM) {
        int m = m0 + tid;
        toks[tid] = (m < cnt) ? g_tok[base + m] : 0;
        wts[tid]  = (m < cnt) ? g_wt[base + m] : 0.f;
    }
    __syncthreads();

    const float* dp = down_w + (size_t)e * NI * NH;

    int a_m = tid >> 3, a_k = (tid & 7) << 2;
    int b_k = tid >> 4, b_n = (tid & 15) << 2;

    // clamped source rows for A
    size_t arow[4];
#pragma unroll
    for (int p = 0; p < 4; p++) {
        int m = m0 + a_m + p * 32;
        arow[p] = (size_t)(base + (m < cnt ? m : m0)) * NI;
    }

#pragma unroll
    for (int p = 0; p < 4; p++) {
        int m = a_m + p * 32;
        float4 v = *(const float4*)(g_act + arow[p] + a_k);
        As[a_k+0][m]=f2tf(v.x); As[a_k+1][m]=f2tf(v.y);
        As[a_k+2][m]=f2tf(v.z); As[a_k+3][m]=f2tf(v.w);
    }
#pragma unroll
    for (int p = 0; p < 2; p++) {
        int k = b_k + p * 16;
        float4 v = *(const float4*)(dp + (size_t)k * NH + n0 + b_n);
        Bs[k][b_n+0]=f2tf(v.x); Bs[k][b_n+1]=f2tf(v.y);
        Bs[k][b_n+2]=f2tf(v.z); Bs[k][b_n+3]=f2tf(v.w);
    }
    __syncthreads();

    int lane = tid & 31, wid = tid >> 5;
    int wm = (wid & 3) * 32, wn = (wid >> 2) * 32;
    int grp = lane >> 2, tig = lane & 3;

    float acc[2][4][4] = {};
    float4 pa[4], pb[2];

    for (int k0 = 0; k0 < NI; k0 += BK) {
        bool nxt = (k0 + BK) < NI;
        if (nxt) {
            int kn = k0 + BK;
#pragma unroll
            for (int p = 0; p < 4; p++)
                pa[p] = *(const float4*)(g_act + arow[p] + kn + a_k);
#pragma unroll
            for (int p = 0; p < 2; p++) {
                int k = b_k + p * 16;
                pb[p] = *(const float4*)(dp + (size_t)(kn + k) * NH + n0 + b_n);
            }
        }

#pragma unroll
        for (int kk = 0; kk < 4; kk++) {
            int k8 = kk * 8;
            unsigned a[2][4];
#pragma unroll
            for (int mi = 0; mi < 2; mi++) {
                int mb = wm + mi * 16 + grp;
                a[mi][0] = As[k8 + tig    ][mb];
                a[mi][1] = As[k8 + tig    ][mb + 8];
                a[mi][2] = As[k8 + tig + 4][mb];
                a[mi][3] = As[k8 + tig + 4][mb + 8];
            }
#pragma unroll
            for (int nj = 0; nj < 4; nj++) {
                int nb = wn + nj * 8 + grp;
                unsigned b[2];
                b[0] = Bs[k8 + tig][nb]; b[1] = Bs[k8 + tig + 4][nb];
                mma8(acc[0][nj], a[0], b);
                mma8(acc[1][nj], a[1], b);
            }
        }
        __syncthreads();
        if (nxt) {
#pragma unroll
            for (int p = 0; p < 4; p++) {
                int m = a_m + p * 32;
                As[a_k+0][m]=f2tf(pa[p].x); As[a_k+1][m]=f2tf(pa[p].y);
                As[a_k+2][m]=f2tf(pa[p].z); As[a_k+3][m]=f2tf(pa[p].w);
            }
#pragma unroll
            for (int p = 0; p < 2; p++) {
                int k = b_k + p * 16;
                Bs[k][b_n+0]=f2tf(pb[p].x); Bs[k][b_n+1]=f2tf(pb[p].y);
                Bs[k][b_n+2]=f2tf(pb[p].z); Bs[k][b_n+3]=f2tf(pb[p].w);
            }
            __syncthreads();
        }
    }

#pragma unroll
    for (int mi = 0; mi < 2; mi++) {
#pragma unroll
        for (int nj = 0; nj < 4; nj++) {
            int mloc = wm + mi * 16 + grp;
            int ncol = n0 + wn + nj * 8 + tig * 2;
#pragma unroll
            for (int h = 0; h < 2; h++) {
                int ml = mloc + h * 8;
                int mr = m0 + ml;
                if (mr < cnt) {
                    int   t = toks[ml];
                    float w = wts[ml];
                    float* dst = out + (size_t)t * NH + ncol;
                    atomicAdd(dst + 0, w * acc[mi][nj][2*h]);
                    atomicAdd(dst + 1, w * acc[mi][nj][2*h + 1]);
                }
            }
        }
    }
}

// ---------------- launch ----------------
extern "C" void kernel_launch(void* const* d_in, const int* in_sizes, int n_in,
                              void* d_out, int out_size)
{
    const float* hidden = (const float*)d_in[0];
    const int*   idx    = (const int*)  d_in[1];
    const float* topw   = (const float*)d_in[2];
    const float* gate_w = (const float*)d_in[3];
    const float* up_w   = (const float*)d_in[4];
    const float* down_w = (const float*)d_in[5];
    float* out = (float*)d_out;

    k_reset<<<1, 32>>>();
    k_count<<<NP / 256, 256>>>(idx);
    k_scan<<<1, 32>>>();
    k_fill<<<NP / 256, 256>>>(idx, topw);
    k_zero<<<(NT * NH / 4) / 256, 256>>>(out);

    dim3 g1(NI / BN, NP / BM, NE);
    k_gemm1<<<g1, 256>>>(hidden, gate_w, up_w);

    dim3 g2(NH / BN, NP / BM, NE);
    k_gemm2<<<g2, 256>>>(down_w, out);
}

// round 3
// speedup vs baseline: 3.0415x; 1.5898x over previous
#include <cuda_runtime.h>
#include <math.h>

#define NT 2048
#define NH 2048
#define NI 1408
#define NE 8
#define TK 2
#define NP (NT*TK)

#define BM   128
#define BN   64
#define BK   32
#define ASTR 36    // [m][k] rows, %32==4 -> frag reads land on banks 4*grp+tig (bijective)
#define BSTR 72    // [k][n] rows, %32==8 -> frag reads 8*tig+grp (bijective)

// ---------------- scratch ----------------
__device__ int   g_cnt[NE];
__device__ int   g_fill[NE];
__device__ int   g_off[NE + 1];
__device__ int   g_tok[NP];
__device__ float g_wt[NP];
__device__ float g_act[(size_t)NP * NI];

// ---------------- routing ----------------
__global__ void k_reset() {
    int i = threadIdx.x;
    if (i < NE) { g_cnt[i] = 0; g_fill[i] = 0; }
}
__global__ void k_count(const int* __restrict__ idx) {
    int i = blockIdx.x * blockDim.x + threadIdx.x;
    if (i < NP) atomicAdd(&g_cnt[idx[i]], 1);
}
__global__ void k_scan() {
    if (threadIdx.x == 0) {
        int s = 0;
        for (int e = 0; e < NE; e++) { g_off[e] = s; s += g_cnt[e]; }
        g_off[NE] = s;
    }
}
__global__ void k_fill(const int* __restrict__ idx, const float* __restrict__ w) {
    int i = blockIdx.x * blockDim.x + threadIdx.x;
    if (i < NP) {
        int e = idx[i];
        int pos = g_off[e] + atomicAdd(&g_fill[e], 1);
        g_tok[pos] = i / TK;
        g_wt[pos]  = w[i];
    }
}
__global__ void k_zero(float* __restrict__ out) {
    int i = blockIdx.x * blockDim.x + threadIdx.x;
    ((float4*)out)[i] = make_float4(0.f, 0.f, 0.f, 0.f);
}

// ---------------- tf32 helpers ----------------
// Round fp32 -> tf32 (round-to-nearest on bit 13) with a single integer add.
// HMMA.tf32 hardware truncates the low 13 mantissa bits, so bits+0x1000 ==
// round-half-up, matching cvt.rna.tf32 to within half an ulp. No F2FP needed.
__device__ __forceinline__ unsigned rtf(float f) {
    return __float_as_uint(f) + 0x1000u;
}
__device__ __forceinline__ uint4 rtf4(float4 v) {
    uint4 r;
    r.x = rtf(v.x); r.y = rtf(v.y); r.z = rtf(v.z); r.w = rtf(v.w);
    return r;
}
__device__ __forceinline__ void mma8(float* c, const unsigned* a, const unsigned* b) {
    asm volatile(
        "mma.sync.aligned.m16n8k8.row.col.f32.tf32.tf32.f32 "
        "{%0,%1,%2,%3},{%4,%5,%6,%7},{%8,%9},{%0,%1,%2,%3};"
        : "+f"(c[0]), "+f"(c[1]), "+f"(c[2]), "+f"(c[3])
        : "r"(a[0]), "r"(a[1]), "r"(a[2]), "r"(a[3]), "r"(b[0]), "r"(b[1]));
}

// smem sizes (words)
#define A_WORDS (2 * BM * ASTR)
#define B_WORDS (2 * BK * BSTR)

// ---------------- GEMM1: act = silu(X Wg) * (X Wu) ----------------
__global__ __launch_bounds__(256) void k_gemm1(
    const float* __restrict__ hidden,
    const float* __restrict__ gate_w,
    const float* __restrict__ up_w)
{
    extern __shared__ unsigned sm[];
    unsigned* sA  = sm;                       // [2][BM][ASTR]
    unsigned* sBg = sA + A_WORDS;             // [2][BK][BSTR]
    unsigned* sBu = sBg + B_WORDS;
    int* toks = (int*)(sBu + B_WORDS);

    int e = blockIdx.z, cnt = g_cnt[e];
    int m0 = blockIdx.y * BM;
    if (m0 >= cnt) return;
    int base = g_off[e];
    int n0 = blockIdx.x * BN;
    int tid = threadIdx.x;

    if (tid < BM) {
        int m = m0 + tid;
        toks[tid] = (m < cnt) ? g_tok[base + m] : g_tok[base];
    }
    __syncthreads();

    const float* gp = gate_w + (size_t)e * NH * NI;
    const float* up = up_w   + (size_t)e * NH * NI;

    int a_m = tid >> 3, a_k = (tid & 7) << 2;   // A: 4 m-passes of 32
    int b_k = tid >> 4, b_n = (tid & 15) << 2;  // B: 2 k-passes of 16

    size_t arow[4];
#pragma unroll
    for (int p = 0; p < 4; p++) arow[p] = (size_t)toks[a_m + p * 32] * NH;

    // prologue: stage 0
#pragma unroll
    for (int p = 0; p < 4; p++) {
        float4 v = *(const float4*)(hidden + arow[p] + a_k);
        *(uint4*)&sA[(size_t)(a_m + p * 32) * ASTR + a_k] = rtf4(v);
    }
#pragma unroll
    for (int p = 0; p < 2; p++) {
        int k = b_k + p * 16;
        float4 vg = *(const float4*)(gp + (size_t)k * NI + n0 + b_n);
        float4 vu = *(const float4*)(up + (size_t)k * NI + n0 + b_n);
        *(uint4*)&sBg[(size_t)k * BSTR + b_n] = rtf4(vg);
        *(uint4*)&sBu[(size_t)k * BSTR + b_n] = rtf4(vu);
    }
    __syncthreads();

    int lane = tid & 31, wid = tid >> 5;
    int wm = (wid & 3) * 32, wn = (wid >> 2) * 32;
    int grp = lane >> 2, tig = lane & 3;

    float accg[2][4][4] = {}, accu[2][4][4] = {};
    float4 pa[4], pg[2], pu[2];

    for (int k0 = 0; k0 < NH; k0 += BK) {
        int s = (k0 / BK) & 1;
        bool nxt = (k0 + BK) < NH;
        if (nxt) {
            int kn = k0 + BK;
#pragma unroll
            for (int p = 0; p < 4; p++)
                pa[p] = *(const float4*)(hidden + arow[p] + kn + a_k);
#pragma unroll
            for (int p = 0; p < 2; p++) {
                int k = b_k + p * 16;
                pg[p] = *(const float4*)(gp + (size_t)(kn + k) * NI + n0 + b_n);
                pu[p] = *(const float4*)(up + (size_t)(kn + k) * NI + n0 + b_n);
            }
        }

        const unsigned* As = sA  + (size_t)s * BM * ASTR;
        const unsigned* Bg = sBg + (size_t)s * BK * BSTR;
        const unsigned* Bu = sBu + (size_t)s * BK * BSTR;

#pragma unroll
        for (int kk = 0; kk < 4; kk++) {
            int k8 = kk * 8;
            unsigned a[2][4];
#pragma unroll
            for (int mi = 0; mi < 2; mi++) {
                int mb = wm + mi * 16 + grp;
                a[mi][0] = As[(mb    ) * ASTR + k8 + tig    ];
                a[mi][1] = As[(mb + 8) * ASTR + k8 + tig    ];
                a[mi][2] = As[(mb    ) * ASTR + k8 + tig + 4];
                a[mi][3] = As[(mb + 8) * ASTR + k8 + tig + 4];
            }
#pragma unroll
            for (int nj = 0; nj < 4; nj++) {
                int nb = wn + nj * 8 + grp;
                unsigned b[2];
                b[0] = Bg[(k8 + tig) * BSTR + nb];
                b[1] = Bg[(k8 + tig + 4) * BSTR + nb];
                mma8(accg[0][nj], a[0], b);
                mma8(accg[1][nj], a[1], b);
                b[0] = Bu[(k8 + tig) * BSTR + nb];
                b[1] = Bu[(k8 + tig + 4) * BSTR + nb];
                mma8(accu[0][nj], a[0], b);
                mma8(accu[1][nj], a[1], b);
            }
        }

        if (nxt) {
            int sn = s ^ 1;
            unsigned* An = sA  + (size_t)sn * BM * ASTR;
            unsigned* Bgn = sBg + (size_t)sn * BK * BSTR;
            unsigned* Bun = sBu + (size_t)sn * BK * BSTR;
#pragma unroll
            for (int p = 0; p < 4; p++)
                *(uint4*)&An[(size_t)(a_m + p * 32) * ASTR + a_k] = rtf4(pa[p]);
#pragma unroll
            for (int p = 0; p < 2; p++) {
                int k = b_k + p * 16;
                *(uint4*)&Bgn[(size_t)k * BSTR + b_n] = rtf4(pg[p]);
                *(uint4*)&Bun[(size_t)k * BSTR + b_n] = rtf4(pu[p]);
            }
        }
        __syncthreads();
    }

    // epilogue: silu(g)*u -> g_act
#pragma unroll
    for (int mi = 0; mi < 2; mi++) {
#pragma unroll
        for (int nj = 0; nj < 4; nj++) {
            int mrow = wm + mi * 16 + grp;
            int ncol = n0 + wn + nj * 8 + tig * 2;
#pragma unroll
            for (int h = 0; h < 2; h++) {
                int mr = m0 + mrow + h * 8;
                if (mr < cnt) {
                    float g0 = accg[mi][nj][2*h],     u0 = accu[mi][nj][2*h];
                    float g1 = accg[mi][nj][2*h + 1], u1 = accu[mi][nj][2*h + 1];
                    float2 v;
                    v.x = (g0 / (1.f + __expf(-g0))) * u0;
                    v.y = (g1 / (1.f + __expf(-g1))) * u1;
                    *(float2*)(g_act + (size_t)(base + mr) * NI + ncol) = v;
                }
            }
        }
    }
}

// ---------------- GEMM2: out[token] += wt * (act . Wd) ----------------
__global__ __launch_bounds__(256) void k_gemm2(
    const float* __restrict__ down_w,
    float* __restrict__ out)
{
    extern __shared__ unsigned sm[];
    unsigned* sA = sm;                         // [2][BM][ASTR]
    unsigned* sB = sA + A_WORDS;               // [2][BK][BSTR]
    int*   toks = (int*)(sB + B_WORDS);
    float* wts  = (float*)(toks + BM);

    int e = blockIdx.z, cnt = g_cnt[e];
    int m0 = blockIdx.y * BM;
    if (m0 >= cnt) return;
    int base = g_off[e];
    int n0 = blockIdx.x * BN;
    int tid = threadIdx.x;

    if (tid < BM) {
        int m = m0 + tid;
        toks[tid] = (m < cnt) ? g_tok[base + m] : 0;
        wts[tid]  = (m < cnt) ? g_wt[base + m] : 0.f;
    }
    __syncthreads();

    const float* dp = down_w + (size_t)e * NI * NH;

    int a_m = tid >> 3, a_k = (tid & 7) << 2;
    int b_k = tid >> 4, b_n = (tid & 15) << 2;

    size_t arow[4];
#pragma unroll
    for (int p = 0; p < 4; p++) {
        int m = m0 + a_m + p * 32;
        arow[p] = (size_t)(base + (m < cnt ? m : m0)) * NI;
    }

#pragma unroll
    for (int p = 0; p < 4; p++) {
        float4 v = *(const float4*)(g_act + arow[p] + a_k);
        *(uint4*)&sA[(size_t)(a_m + p * 32) * ASTR + a_k] = rtf4(v);
    }
#pragma unroll
    for (int p = 0; p < 2; p++) {
        int k = b_k + p * 16;
        float4 v = *(const float4*)(dp + (size_t)k * NH + n0 + b_n);
        *(uint4*)&sB[(size_t)k * BSTR + b_n] = rtf4(v);
    }
    __syncthreads();

    int lane = tid & 31, wid = tid >> 5;
    int wm = (wid & 3) * 32, wn = (wid >> 2) * 32;
    int grp = lane >> 2, tig = lane & 3;

    float acc[2][4][4] = {};
    float4 pa[4], pb[2];

    for (int k0 = 0; k0 < NI; k0 += BK) {
        int s = (k0 / BK) & 1;
        bool nxt = (k0 + BK) < NI;
        if (nxt) {
            int kn = k0 + BK;
#pragma unroll
            for (int p = 0; p < 4; p++)
                pa[p] = *(const float4*)(g_act + arow[p] + kn + a_k);
#pragma unroll
            for (int p = 0; p < 2; p++) {
                int k = b_k + p * 16;
                pb[p] = *(const float4*)(dp + (size_t)(kn + k) * NH + n0 + b_n);
            }
        }

        const unsigned* As = sA + (size_t)s * BM * ASTR;
        const unsigned* Bs = sB + (size_t)s * BK * BSTR;

#pragma unroll
        for (int kk = 0; kk < 4; kk++) {
            int k8 = kk * 8;
            unsigned a[2][4];
#pragma unroll
            for (int mi = 0; mi < 2; mi++) {
                int mb = wm + mi * 16 + grp;
                a[mi][0] = As[(mb    ) * ASTR + k8 + tig    ];
                a[mi][1] = As[(mb + 8) * ASTR + k8 + tig    ];
                a[mi][2] = As[(mb    ) * ASTR + k8 + tig + 4];
                a[mi][3] = As[(mb + 8) * ASTR + k8 + tig + 4];
            }
#pragma unroll
            for (int nj = 0; nj < 4; nj++) {
                int nb = wn + nj * 8 + grp;
                unsigned b[2];
                b[0] = Bs[(k8 + tig) * BSTR + nb];
                b[1] = Bs[(k8 + tig + 4) * BSTR + nb];
                mma8(acc[0][nj], a[0], b);
                mma8(acc[1][nj], a[1], b);
            }
        }

        if (nxt) {
            int sn = s ^ 1;
            unsigned* An = sA + (size_t)sn * BM * ASTR;
            unsigned* Bn = sB + (size_t)sn * BK * BSTR;
#pragma unroll
            for (int p = 0; p < 4; p++)
                *(uint4*)&An[(size_t)(a_m + p * 32) * ASTR + a_k] = rtf4(pa[p]);
#pragma unroll
            for (int p = 0; p < 2; p++) {
                int k = b_k + p * 16;
                *(uint4*)&Bn[(size_t)k * BSTR + b_n] = rtf4(pb[p]);
            }
        }
        __syncthreads();
    }

#pragma unroll
    for (int mi = 0; mi < 2; mi++) {
#pragma unroll
        for (int nj = 0; nj < 4; nj++) {
            int mloc = wm + mi * 16 + grp;
            int ncol = n0 + wn + nj * 8 + tig * 2;
#pragma unroll
            for (int h = 0; h < 2; h++) {
                int ml = mloc + h * 8;
                int mr = m0 + ml;
                if (mr < cnt) {
                    int   t = toks[ml];
                    float w = wts[ml];
                    float* dst = out + (size_t)t * NH + ncol;
                    asm volatile("red.global.add.v2.f32 [%0], {%1,%2};"
                                 :: "l"(dst), "f"(w * acc[mi][nj][2*h]),
                                    "f"(w * acc[mi][nj][2*h + 1]) : "memory");
                }
            }
        }
    }
}

// ---------------- launch ----------------
extern "C" void kernel_launch(void* const* d_in, const int* in_sizes, int n_in,
                              void* d_out, int out_size)
{
    const float* hidden = (const float*)d_in[0];
    const int*   idx    = (const int*)  d_in[1];
    const float* topw   = (const float*)d_in[2];
    const float* gate_w = (const float*)d_in[3];
    const float* up_w   = (const float*)d_in[4];
    const float* down_w = (const float*)d_in[5];
    float* out = (float*)d_out;

    int smem1 = (A_WORDS + 2 * B_WORDS) * 4 + BM * 4;
    int smem2 = (A_WORDS + B_WORDS) * 4 + BM * 8;
    static int configured = 0;
    if (!configured) {
        cudaFuncSetAttribute(k_gemm1, cudaFuncAttributeMaxDynamicSharedMemorySize, smem1);
        cudaFuncSetAttribute(k_gemm2, cudaFuncAttributeMaxDynamicSharedMemorySize, smem2);
        configured = 1;
    }

    k_reset<<<1, 32>>>();
    k_count<<<NP / 256, 256>>>(idx);
    k_scan<<<1, 32>>>();
    k_fill<<<NP / 256, 256>>>(idx, topw);
    k_zero<<<(NT * NH / 4) / 256, 256>>>(out);

    dim3 g1(NI / BN, NP / BM, NE);
    k_gemm1<<<g1, 256, smem1>>>(hidden, gate_w, up_w);

    dim3 g2(NH / BN, NP / BM, NE);
    k_gemm2<<<g2, 256, smem2>>>(down_w, out);
}